// round 8
// baseline (speedup 1.0000x reference)
#include <cuda_runtime.h>

// ---------------------------------------------------------------------------
// DECOLA Stage2 assigner — label-bucketed, 3 wide kernels, branchless top-4.
// Inputs (metadata order):
//   0: pred_logits_match (B,N,1) f32   -- unused
//   1: pred_boxes        (B,N,4) f32   -- unused
//   2: init_reference    (B,N,4) f32   -- proposals (cxcywh)
//   3: prompt_inds       (B,N)   i32
//   4: gt_labels         (B,M)   i32
//   5: gt_boxes          (B,M,4) f32
//   6: max_k             scalar  i32   (k derived from out_size)
// Output: concat(rows, cols, valid, sel_iou) each (B,M,k), float32.
// ---------------------------------------------------------------------------

#define BB      16            // batch (fixed for this problem)
#define NL      128           // label slots (L=80, padded)
#define PCAP    256           // proposal bucket capacity (mean 37.5)
#define GCAP    64            // gt bucket capacity (mean 3.75)
#define NBK     (BB * NL)     // 2048 buckets
#define MAX_BN  49152
#define MAX_BM  8192
#define MAXM    384           // smem staging capacity per batch (M=300)
#define TOPK    4
#define IMAXI   0x7fffffff

// __device__ globals are zero-initialized at module load; the bucket counters
// are re-zeroed at the end of k_colsout, so every call starts clean.
__device__ float4 g_pxy[MAX_BN];
__device__ float  g_pa [MAX_BN];
__device__ int    d_pcnt[NBK];
__device__ float4 p_bx[NBK * PCAP];
__device__ float  p_ba[NBK * PCAP];
__device__ int    p_bi[NBK * PCAP];
__device__ int    d_gcnt[NBK];
__device__ float4 gt_bx[NBK * GCAP];
__device__ float  gt_ba[NBK * GCAP];
__device__ int    gt_bm[NBK * GCAP];
__device__ float4 g_gxy[MAX_BM];
__device__ float  g_ga [MAX_BM];
__device__ float  g_gmax[MAX_BM];
__device__ float  g_topv[MAX_BM * TOPK];
__device__ int    g_topi[MAX_BM * TOPK];

// IoU from explicit _rn intrinsics so the rows pass and cols pass produce
// BITWISE-identical values (lq needs v == gmax). Both passes feed this exact
// function bit-identical stored copies of the same converted boxes.
__device__ __forceinline__ float iou_fn(float4 g, float ga, float4 p, float pa) {
    float x0 = fmaxf(g.x, p.x);
    float y0 = fmaxf(g.y, p.y);
    float x1 = fminf(g.z, p.z);
    float y1 = fminf(g.w, p.w);
    float w  = fmaxf(__fsub_rn(x1, x0), 0.0f);
    float h  = fmaxf(__fsub_rn(y1, y0), 0.0f);
    float it = __fmul_rn(w, h);
    float un = __fsub_rn(__fadd_rn(ga, pa), it);
    return __fdiv_rn(it, fmaxf(un, 1e-9f));
}

// BRANCHLESS insert of (v,i) into a 4-entry list sorted by (value desc,
// index asc): compare-carry chain, pure setp/sel — no BSSY/BSYNC divergence.
// Strict total order (indices distinct) -> insert-order independent; matches
// jax.lax.top_k stability (lower index first among equal values).
__device__ __forceinline__ void ins4(float v, int i, float tv[TOPK], int ti[TOPK]) {
#pragma unroll
    for (int j = 0; j < TOPK; j++) {
        bool sw = (v > tv[j]) || (v == tv[j] && i < ti[j]);
        float cv = sw ? tv[j] : v;
        int   ci = sw ? ti[j] : i;
        tv[j] = sw ? v : tv[j];
        ti[j] = sw ? i : ti[j];
        v = cv; i = ci;
    }
}

__device__ __forceinline__ float4 cxcywh_to_xyxy(float4 c) {
    float4 x;
    x.x = c.x - 0.5f * c.z; x.y = c.y - 0.5f * c.w;
    x.z = c.x + 0.5f * c.z; x.w = c.y + 0.5f * c.w;
    return x;
}

// ---------------- Kernel 1: convert + bucket-scatter (wide) ----------------
__global__ void k_build(const float4* __restrict__ props,
                        const float4* __restrict__ gts,
                        const int* __restrict__ pinds,
                        const int* __restrict__ glabels,
                        int BN, int BM, int N, int M) {
    int idx = blockIdx.x * blockDim.x + threadIdx.x;
    if (idx < BN) {
        float4 x = cxcywh_to_xyxy(props[idx]);
        float  a = __fmul_rn(__fsub_rn(x.z, x.x), __fsub_rn(x.w, x.y));
        g_pxy[idx] = x;
        g_pa [idx] = a;
        int b  = idx / N;
        int bk = b * NL + pinds[idx];
        int s  = atomicAdd(&d_pcnt[bk], 1);
        if (s < PCAP) {
            p_bx[bk * PCAP + s] = x;
            p_ba[bk * PCAP + s] = a;
            p_bi[bk * PCAP + s] = idx - b * N;
        }
    } else if (idx < BN + BM) {
        int j = idx - BN;
        float4 x = cxcywh_to_xyxy(gts[j]);
        float  a = __fmul_rn(__fsub_rn(x.z, x.x), __fsub_rn(x.w, x.y));
        g_gxy[j] = x;
        g_ga [j] = a;
        int b  = j / M;
        int bk = b * NL + glabels[j];
        int s  = atomicAdd(&d_gcnt[bk], 1);
        if (s < GCAP) {
            gt_bx[bk * GCAP + s] = x;
            gt_ba[bk * GCAP + s] = a;
            gt_bm[bk * GCAP + s] = j - b * M;
        }
    }
}

// -------- Kernel 2: 8 lanes per GT row: gmax + stable top-4 (wide) --------
__global__ __launch_bounds__(256) void k_rows(
        const int* __restrict__ glabels, int M, int BM) {
    int t    = blockIdx.x * blockDim.x + threadIdx.x;
    int bm   = t >> 3;                   // 8 lanes per GT
    if (bm >= BM) return;                // whole warps only (BM*8 % 32 == 0)
    int sub  = t & 7;
    int b    = bm / M;
    int bk   = b * NL + glabels[bm];
    int cnt  = min(d_pcnt[bk], PCAP);
    int base = bk * PCAP;

    float4 g = g_gxy[bm];
    float ga = g_ga[bm];

    float tv[TOPK] = {-1.f, -1.f, -1.f, -1.f};
    int   ti[TOPK] = {IMAXI, IMAXI, IMAXI, IMAXI};

    for (int e = sub; e < cnt; e += 8) {
        float v = iou_fn(g, ga, p_bx[base + e], p_ba[base + e]);
        ins4(v, p_bi[base + e], tv, ti);
    }

    // 3-step butterfly within each aligned 8-lane group.
#pragma unroll
    for (int off = 4; off > 0; off >>= 1) {
        float ov[TOPK]; int oi[TOPK];
#pragma unroll
        for (int j = 0; j < TOPK; j++) {
            ov[j] = __shfl_xor_sync(0xffffffffu, tv[j], off);
            oi[j] = __shfl_xor_sync(0xffffffffu, ti[j], off);
        }
#pragma unroll
        for (int j = 0; j < TOPK; j++) ins4(ov[j], oi[j], tv, ti);
    }

    if (sub == 0) {
        g_gmax[bm] = tv[0];              // -1 when no matched proposal (== ref NEG)
#pragma unroll
        for (int j = 0; j < TOPK; j++) {
            g_topv[bm * TOPK + j] = tv[j];
            g_topi[bm * TOPK + j] = ti[j];
        }
    }
}

// -------- Kernel 3: cols pass + output, one block per batch --------
// Stage this batch's GT buckets compactly in smem, scan proposals (coalesced,
// L2-hot), accumulate counts in smem, then write the 4 output streams and
// reset this batch's bucket counters for the next invocation.
__global__ __launch_bounds__(1024) void k_colsout(
        const int* __restrict__ pinds,
        float* __restrict__ out,
        int N, int M, int B, int K) {
    __shared__ int    soff[NL + 1];
    __shared__ float4 s_box [MAXM];
    __shared__ float  s_area[MAXM];
    __shared__ float  s_gm  [MAXM];
    __shared__ int    s_m   [MAXM];
    __shared__ int    s_cnt [MAXM];

    int b   = blockIdx.x;
    int tid = threadIdx.x;

    // per-label counts + Hillis-Steele prefix sum (NL = 128)
    int mycnt = 0;
    if (tid < NL) {
        mycnt = min(d_gcnt[b * NL + tid], GCAP);
        soff[tid + 1] = mycnt;
        if (tid == 0) soff[0] = 0;
    }
    for (int m = tid; m < M; m += blockDim.x) s_cnt[m] = 0;
    __syncthreads();
#pragma unroll
    for (int d = 1; d < NL; d <<= 1) {
        int v = 0;
        if (tid < NL) {
            v = soff[tid + 1];
            if (tid + 1 > d) v += soff[tid + 1 - d];
        }
        __syncthreads();
        if (tid < NL) soff[tid + 1] = v;
        __syncthreads();
    }

    // stage bucket entries compactly
    if (tid < NL) {
        int base = (b * NL + tid) * GCAP;
        int o    = soff[tid];
        for (int s = 0; s < mycnt; s++) {
            s_box [o + s] = gt_bx[base + s];
            s_area[o + s] = gt_ba[base + s];
            int m         = gt_bm[base + s];
            s_m   [o + s] = m;
            s_gm  [o + s] = g_gmax[b * M + m];
        }
    }
    __syncthreads();

    // cols pass: each thread handles ceil(N/1024) proposals
    for (int n = tid; n < N; n += blockDim.x) {
        int    pv = pinds[b * N + n];
        float4 p  = g_pxy[b * N + n];
        float  pa = g_pa [b * N + n];
        int o0 = soff[pv];
        int o1 = soff[pv + 1];

        float best = -2.0f;
        int   bg   = IMAXI;
        bool  lq   = false;
        for (int e = o0; e < o1; e++) {
            float v = iou_fn(s_box[e], s_area[e], p, pa);
            int   m = s_m[e];
            // lexicographic (v desc, m asc) == JAX first-index argmax over
            // matched entries; unmatched rows (-1) never win when a match
            // exists, and pos=false when none exists.
            bool bt = (v > best) || (v == best && m < bg);
            best = bt ? v : best;
            bg   = bt ? m : bg;
            lq   = lq || (v == s_gm[e]);     // bitwise vs k_rows
        }
        if (best >= 0.6f || lq) atomicAdd(&s_cnt[bg], 1);
    }
    __syncthreads();

    // output: rows | cols | valid | sel_iou (coalesced within batch slab)
    {
        int S = B * M * K;
        for (int e = tid; e < M * K; e += blockDim.x) {
            int  m   = e / K;
            int  j   = e - m * K;
            bool val = j < min(s_cnt[m], K);
            int  bm  = b * M + m;
            int  o   = b * M * K + e;
            out[        o] = val ? (float)g_topi[bm * TOPK + j] : -1.0f;
            out[    S + o] = val ? (float)m                     : -1.0f;
            out[2 * S + o] = val ? 1.0f : 0.0f;
            out[3 * S + o] = val ? g_topv[bm * TOPK + j]        : 0.0f;
        }
    }

    // reset this batch's bucket counters for the next invocation
    if (tid < NL) {
        d_pcnt[b * NL + tid] = 0;
        d_gcnt[b * NL + tid] = 0;
    }
}

// ---------------------------------------------------------------------------
extern "C" void kernel_launch(void* const* d_in, const int* in_sizes, int n_in,
                              void* d_out, int out_size) {
    const float4* props   = (const float4*)d_in[2];
    const int*    pinds   = (const int*)   d_in[3];
    const int*    glabels = (const int*)   d_in[4];
    const float4* gts     = (const float4*)d_in[5];

    const int B  = BB;
    int BN = in_sizes[3];
    int BM = in_sizes[4];
    int N  = BN / B;
    int M  = BM / B;
    int K  = out_size / (4 * BM);
    if (K > TOPK) K = TOPK;
    if (K < 1)    K = 1;

    k_build  <<<(BN + BM + 255) / 256, 256>>>(props, gts, pinds, glabels, BN, BM, N, M);
    k_rows   <<<(BM * 8 + 255) / 256, 256>>>(glabels, M, BM);
    k_colsout<<<B, 1024>>>(pinds, (float*)d_out, N, M, B, K);
}

// round 9
// speedup vs baseline: 1.6104x; 1.6104x over previous
#include <cuda_runtime.h>

// ---------------------------------------------------------------------------
// DECOLA Stage2 assigner — single kernel, one block per (label, batch) bucket.
//
// Key fact: match = (gt_label == prompt_ind), so the entire assignment
// decomposes per (batch,label) bucket: a GT only ever interacts with
// proposals of its own label, best_gt for a proposal is within its label's
// GTs, and each GT's output row is produced by exactly one bucket. Hence one
// self-contained block per bucket, chip-wide grid (128x16 = 2048 blocks),
// zero global scratch, zero inter-kernel traffic, ONE launch.
//
// Inputs (metadata order):
//   0: pred_logits_match (B,N,1) f32   -- unused
//   1: pred_boxes        (B,N,4) f32   -- unused
//   2: init_reference    (B,N,4) f32   -- proposals (cxcywh)
//   3: prompt_inds       (B,N)   i32
//   4: gt_labels         (B,M)   i32
//   5: gt_boxes          (B,M,4) f32
//   6: max_k             scalar  i32   (k derived from out_size)
// Output: concat(rows, cols, valid, sel_iou) each (B,M,k), float32.
// ---------------------------------------------------------------------------

#define BB      16            // batch (fixed for this problem)
#define NL      128           // label slots (L=80 < 128)
#define PCAP    192           // proposals per bucket cap (mean 37.5, sd 6 -> 25 sigma)
#define GCAP    32            // gts per bucket cap (mean 3.75, sd 1.9)
#define TOPK    4
#define THREADS 128
#define IMAXI   0x7fffffff

// IoU from explicit _rn intrinsics. Rows pass and cols pass call this same
// function on the SAME smem-resident box bits, so lq's (v == gmax) equality
// is exact by construction.
__device__ __forceinline__ float iou_fn(float4 g, float ga, float4 p, float pa) {
    float x0 = fmaxf(g.x, p.x);
    float y0 = fmaxf(g.y, p.y);
    float x1 = fminf(g.z, p.z);
    float y1 = fminf(g.w, p.w);
    float w  = fmaxf(__fsub_rn(x1, x0), 0.0f);
    float h  = fmaxf(__fsub_rn(y1, y0), 0.0f);
    float it = __fmul_rn(w, h);
    float un = __fsub_rn(__fadd_rn(ga, pa), it);
    return __fdiv_rn(it, fmaxf(un, 1e-9f));
}

// BRANCHLESS insert of (v,i) into a 4-entry list sorted by (value desc,
// index asc): compare-carry chain, pure setp/sel. Strict total order
// (indices distinct) -> insert-order independent; matches jax.lax.top_k
// stability (lower index first among equal values).
__device__ __forceinline__ void ins4(float v, int i, float tv[TOPK], int ti[TOPK]) {
#pragma unroll
    for (int j = 0; j < TOPK; j++) {
        bool sw = (v > tv[j]) || (v == tv[j] && i < ti[j]);
        float cv = sw ? tv[j] : v;
        int   ci = sw ? ti[j] : i;
        tv[j] = sw ? v : tv[j];
        ti[j] = sw ? i : ti[j];
        v = cv; i = ci;
    }
}

__device__ __forceinline__ float4 cxcywh_to_xyxy(float4 c) {
    float4 x;
    x.x = c.x - 0.5f * c.z; x.y = c.y - 0.5f * c.w;
    x.z = c.x + 0.5f * c.z; x.w = c.y + 0.5f * c.w;
    return x;
}

__global__ __launch_bounds__(THREADS)
void k_bucket(const float4* __restrict__ props,
              const float4* __restrict__ gts,
              const int*    __restrict__ pinds,
              const int*    __restrict__ glabels,
              float*        __restrict__ out,
              int N, int M, int B, int K) {
    __shared__ int    s_pcnt, s_gcnt;
    __shared__ int    s_pn  [PCAP];   // proposal indices n
    __shared__ float4 s_pbox[PCAP];
    __shared__ float  s_pa  [PCAP];
    __shared__ int    s_gm  [GCAP];   // gt indices m
    __shared__ float4 s_gbox[GCAP];
    __shared__ float  s_ga  [GCAP];
    __shared__ float  s_gmax[GCAP];
    __shared__ float  s_tv  [GCAP * TOPK];
    __shared__ int    s_ti  [GCAP * TOPK];
    __shared__ int    s_cnt [GCAP];

    const int l   = blockIdx.x;       // label
    const int b   = blockIdx.y;       // batch
    const int tid = threadIdx.x;

    if (tid == 0) { s_pcnt = 0; s_gcnt = 0; }
    __syncthreads();

    // ---- scan gt labels; early-exit if this label has no GT ----
    for (int m = tid; m < M; m += THREADS) {
        if (glabels[b * M + m] == l) {
            int s = atomicAdd(&s_gcnt, 1);
            if (s < GCAP) s_gm[s] = m;
        }
    }
    __syncthreads();
    int gcnt = min(s_gcnt, GCAP);
    if (gcnt == 0) return;            // no GT of this label: no outputs here

    // ---- scan prompt_inds for matching proposals (coalesced, L2-broadcast) ----
    for (int n = tid; n < N; n += THREADS) {
        if (pinds[b * N + n] == l) {
            int s = atomicAdd(&s_pcnt, 1);
            if (s < PCAP) s_pn[s] = n;
        }
    }
    __syncthreads();
    int pcnt = min(s_pcnt, PCAP);

    // ---- load + convert matched boxes into smem (each read exactly once chip-wide) ----
    for (int i = tid; i < pcnt; i += THREADS) {
        float4 x = cxcywh_to_xyxy(props[b * N + s_pn[i]]);
        s_pbox[i] = x;
        s_pa [i]  = __fmul_rn(__fsub_rn(x.z, x.x), __fsub_rn(x.w, x.y));
    }
    for (int i = tid; i < gcnt; i += THREADS) {
        float4 x = cxcywh_to_xyxy(gts[b * M + s_gm[i]]);
        s_gbox[i] = x;
        s_ga [i]  = __fmul_rn(__fsub_rn(x.z, x.x), __fsub_rn(x.w, x.y));
        s_cnt[i]  = 0;
    }
    __syncthreads();

    // ---- rows pass: one warp per GT, lanes stride proposals, butterfly top-4 ----
    {
        int w    = tid >> 5;
        int lane = tid & 31;
        for (int g = w; g < gcnt; g += THREADS / 32) {   // warp-uniform trip count
            float4 gb = s_gbox[g];
            float  ga = s_ga[g];
            float tv[TOPK] = {-1.f, -1.f, -1.f, -1.f};
            int   ti[TOPK] = {IMAXI, IMAXI, IMAXI, IMAXI};
            for (int e = lane; e < pcnt; e += 32) {
                float v = iou_fn(gb, ga, s_pbox[e], s_pa[e]);
                ins4(v, s_pn[e], tv, ti);
            }
#pragma unroll
            for (int off = 16; off > 0; off >>= 1) {
                float ov[TOPK]; int oi[TOPK];
#pragma unroll
                for (int j = 0; j < TOPK; j++) {
                    ov[j] = __shfl_xor_sync(0xffffffffu, tv[j], off);
                    oi[j] = __shfl_xor_sync(0xffffffffu, ti[j], off);
                }
#pragma unroll
                for (int j = 0; j < TOPK; j++) ins4(ov[j], oi[j], tv, ti);
            }
            if (lane == 0) {
                s_gmax[g] = tv[0];        // -1 when bucket has no proposals (== ref NEG)
#pragma unroll
                for (int j = 0; j < TOPK; j++) {
                    s_tv[g * TOPK + j] = tv[j];
                    s_ti[g * TOPK + j] = ti[j];
                }
            }
        }
    }
    __syncthreads();

    // ---- cols pass: per matched proposal, argmax over bucket GTs + lq + counts ----
    for (int i = tid; i < pcnt; i += THREADS) {
        float4 p  = s_pbox[i];
        float  pa = s_pa[i];
        float best = -2.0f;
        int   bgm  = IMAXI;   // gt index m for tie-break (JAX first-index argmax)
        int   bgs  = 0;       // gt slot for s_cnt
        bool  lq   = false;
        for (int e = 0; e < gcnt; e++) {
            float v = iou_fn(s_gbox[e], s_ga[e], p, pa);
            int   m = s_gm[e];
            // lexicographic (v desc, m asc): equals first-index argmax over
            // matched rows; unmatched rows (-1) never beat a matched iou>=0,
            // and pos=false when no match exists (handled by bucket scoping).
            bool bt = (v > best) || (v == best && m < bgm);
            best = bt ? v : best;
            bgm  = bt ? m : bgm;
            bgs  = bt ? e : bgs;
            lq   = lq || (v == s_gmax[e]);    // bitwise: same fn, same smem bits
        }
        if (best >= 0.6f || lq) atomicAdd(&s_cnt[bgs], 1);
    }
    __syncthreads();

    // ---- output: rows | cols | valid | sel_iou for this bucket's GTs ----
    {
        int S = B * M * K;
        for (int e = tid; e < gcnt * K; e += THREADS) {
            int  g    = e / K;
            int  j    = e - g * K;
            int  m    = s_gm[g];
            bool val  = j < min(s_cnt[g], K);
            int  o    = (b * M + m) * K + j;
            out[        o] = val ? (float)s_ti[g * TOPK + j] : -1.0f;
            out[    S + o] = val ? (float)m                  : -1.0f;
            out[2 * S + o] = val ? 1.0f : 0.0f;
            out[3 * S + o] = val ? s_tv[g * TOPK + j]        : 0.0f;
        }
    }
}

// ---------------------------------------------------------------------------
extern "C" void kernel_launch(void* const* d_in, const int* in_sizes, int n_in,
                              void* d_out, int out_size) {
    const float4* props   = (const float4*)d_in[2];
    const int*    pinds   = (const int*)   d_in[3];
    const int*    glabels = (const int*)   d_in[4];
    const float4* gts     = (const float4*)d_in[5];

    const int B  = BB;
    int BN = in_sizes[3];
    int BM = in_sizes[4];
    int N  = BN / B;
    int M  = BM / B;
    int K  = out_size / (4 * BM);
    if (K > TOPK) K = TOPK;
    if (K < 1)    K = 1;

    k_bucket<<<dim3(NL, B), THREADS>>>(props, gts, pinds, glabels,
                                       (float*)d_out, N, M, B, K);
}

// round 10
// speedup vs baseline: 1.6188x; 1.0052x over previous
#include <cuda_runtime.h>

// ---------------------------------------------------------------------------
// DECOLA Stage2 assigner — single kernel, one block per (label, batch) bucket.
//
// Key fact: match = (gt_label == prompt_ind), so the entire assignment
// decomposes per (batch,label) bucket: a GT only ever interacts with
// proposals of its own label, best_gt for a proposal is within its label's
// GTs, and each GT's output row is produced by exactly one bucket. Hence one
// self-contained block per bucket, chip-wide grid (128x16 = 2048 blocks),
// zero global scratch, zero inter-kernel traffic, ONE launch.
//
// Inputs (metadata order):
//   0: pred_logits_match (B,N,1) f32   -- unused
//   1: pred_boxes        (B,N,4) f32   -- unused
//   2: init_reference    (B,N,4) f32   -- proposals (cxcywh)
//   3: prompt_inds       (B,N)   i32
//   4: gt_labels         (B,M)   i32
//   5: gt_boxes          (B,M,4) f32
//   6: max_k             scalar  i32   (k derived from out_size)
// Output: concat(rows, cols, valid, sel_iou) each (B,M,k), float32.
// ---------------------------------------------------------------------------

#define BB      16            // batch (fixed for this problem)
#define NL      128           // label slots (L=80 < 128)
#define PCAP    192           // proposals per bucket cap (mean 37.5, sd 6 -> 25 sigma)
#define GCAP    32            // gts per bucket cap (mean 3.75, sd 1.9)
#define TOPK    4
#define THREADS 128
#define IMAXI   0x7fffffff

// IoU from explicit _rn intrinsics. Rows pass and cols pass call this same
// function on the SAME smem-resident box bits, so lq's (v == gmax) equality
// is exact by construction.
__device__ __forceinline__ float iou_fn(float4 g, float ga, float4 p, float pa) {
    float x0 = fmaxf(g.x, p.x);
    float y0 = fmaxf(g.y, p.y);
    float x1 = fminf(g.z, p.z);
    float y1 = fminf(g.w, p.w);
    float w  = fmaxf(__fsub_rn(x1, x0), 0.0f);
    float h  = fmaxf(__fsub_rn(y1, y0), 0.0f);
    float it = __fmul_rn(w, h);
    float un = __fsub_rn(__fadd_rn(ga, pa), it);
    return __fdiv_rn(it, fmaxf(un, 1e-9f));
}

// BRANCHLESS insert of (v,i) into a 4-entry list sorted by (value desc,
// index asc): compare-carry chain, pure setp/sel. Strict total order
// (indices distinct) -> insert-order independent; matches jax.lax.top_k
// stability (lower index first among equal values).
__device__ __forceinline__ void ins4(float v, int i, float tv[TOPK], int ti[TOPK]) {
#pragma unroll
    for (int j = 0; j < TOPK; j++) {
        bool sw = (v > tv[j]) || (v == tv[j] && i < ti[j]);
        float cv = sw ? tv[j] : v;
        int   ci = sw ? ti[j] : i;
        tv[j] = sw ? v : tv[j];
        ti[j] = sw ? i : ti[j];
        v = cv; i = ci;
    }
}

__device__ __forceinline__ float4 cxcywh_to_xyxy(float4 c) {
    float4 x;
    x.x = c.x - 0.5f * c.z; x.y = c.y - 0.5f * c.w;
    x.z = c.x + 0.5f * c.z; x.w = c.y + 0.5f * c.w;
    return x;
}

__global__ __launch_bounds__(THREADS)
void k_bucket(const float4* __restrict__ props,
              const float4* __restrict__ gts,
              const int*    __restrict__ pinds,
              const int*    __restrict__ glabels,
              float*        __restrict__ out,
              int N, int M, int B, int K) {
    __shared__ int    s_pcnt, s_gcnt;
    __shared__ int    s_pn  [PCAP];   // proposal indices n
    __shared__ float4 s_pbox[PCAP];
    __shared__ float  s_pa  [PCAP];
    __shared__ int    s_gm  [GCAP];   // gt indices m
    __shared__ float4 s_gbox[GCAP];
    __shared__ float  s_ga  [GCAP];
    __shared__ float  s_gmax[GCAP];
    __shared__ float  s_tv  [GCAP * TOPK];
    __shared__ int    s_ti  [GCAP * TOPK];
    __shared__ int    s_cnt [GCAP];

    const int l   = blockIdx.x;       // label
    const int b   = blockIdx.y;       // batch
    const int tid = threadIdx.x;

    if (tid == 0) { s_pcnt = 0; s_gcnt = 0; }
    __syncthreads();

    // ---- scan gt labels; early-exit if this label has no GT ----
    for (int m = tid; m < M; m += THREADS) {
        if (glabels[b * M + m] == l) {
            int s = atomicAdd(&s_gcnt, 1);
            if (s < GCAP) s_gm[s] = m;
        }
    }
    __syncthreads();
    int gcnt = min(s_gcnt, GCAP);
    if (gcnt == 0) return;            // no GT of this label: no outputs here

    // ---- scan prompt_inds for matching proposals (coalesced, L2-broadcast) ----
    for (int n = tid; n < N; n += THREADS) {
        if (pinds[b * N + n] == l) {
            int s = atomicAdd(&s_pcnt, 1);
            if (s < PCAP) s_pn[s] = n;
        }
    }
    __syncthreads();
    int pcnt = min(s_pcnt, PCAP);

    // ---- load + convert matched boxes into smem (each read exactly once chip-wide) ----
    for (int i = tid; i < pcnt; i += THREADS) {
        float4 x = cxcywh_to_xyxy(props[b * N + s_pn[i]]);
        s_pbox[i] = x;
        s_pa [i]  = __fmul_rn(__fsub_rn(x.z, x.x), __fsub_rn(x.w, x.y));
    }
    for (int i = tid; i < gcnt; i += THREADS) {
        float4 x = cxcywh_to_xyxy(gts[b * M + s_gm[i]]);
        s_gbox[i] = x;
        s_ga [i]  = __fmul_rn(__fsub_rn(x.z, x.x), __fsub_rn(x.w, x.y));
        s_cnt[i]  = 0;
    }
    __syncthreads();

    // ---- rows pass: one warp per GT, lanes stride proposals, butterfly top-4 ----
    {
        int w    = tid >> 5;
        int lane = tid & 31;
        for (int g = w; g < gcnt; g += THREADS / 32) {   // warp-uniform trip count
            float4 gb = s_gbox[g];
            float  ga = s_ga[g];
            float tv[TOPK] = {-1.f, -1.f, -1.f, -1.f};
            int   ti[TOPK] = {IMAXI, IMAXI, IMAXI, IMAXI};
            for (int e = lane; e < pcnt; e += 32) {
                float v = iou_fn(gb, ga, s_pbox[e], s_pa[e]);
                ins4(v, s_pn[e], tv, ti);
            }
#pragma unroll
            for (int off = 16; off > 0; off >>= 1) {
                float ov[TOPK]; int oi[TOPK];
#pragma unroll
                for (int j = 0; j < TOPK; j++) {
                    ov[j] = __shfl_xor_sync(0xffffffffu, tv[j], off);
                    oi[j] = __shfl_xor_sync(0xffffffffu, ti[j], off);
                }
#pragma unroll
                for (int j = 0; j < TOPK; j++) ins4(ov[j], oi[j], tv, ti);
            }
            if (lane == 0) {
                s_gmax[g] = tv[0];        // -1 when bucket has no proposals (== ref NEG)
#pragma unroll
                for (int j = 0; j < TOPK; j++) {
                    s_tv[g * TOPK + j] = tv[j];
                    s_ti[g * TOPK + j] = ti[j];
                }
            }
        }
    }
    __syncthreads();

    // ---- cols pass: per matched proposal, argmax over bucket GTs + lq + counts ----
    for (int i = tid; i < pcnt; i += THREADS) {
        float4 p  = s_pbox[i];
        float  pa = s_pa[i];
        float best = -2.0f;
        int   bgm  = IMAXI;   // gt index m for tie-break (JAX first-index argmax)
        int   bgs  = 0;       // gt slot for s_cnt
        bool  lq   = false;
        for (int e = 0; e < gcnt; e++) {
            float v = iou_fn(s_gbox[e], s_ga[e], p, pa);
            int   m = s_gm[e];
            // lexicographic (v desc, m asc): equals first-index argmax over
            // matched rows; unmatched rows (-1) never beat a matched iou>=0,
            // and pos=false when no match exists (handled by bucket scoping).
            bool bt = (v > best) || (v == best && m < bgm);
            best = bt ? v : best;
            bgm  = bt ? m : bgm;
            bgs  = bt ? e : bgs;
            lq   = lq || (v == s_gmax[e]);    // bitwise: same fn, same smem bits
        }
        if (best >= 0.6f || lq) atomicAdd(&s_cnt[bgs], 1);
    }
    __syncthreads();

    // ---- output: rows | cols | valid | sel_iou for this bucket's GTs ----
    {
        int S = B * M * K;
        for (int e = tid; e < gcnt * K; e += THREADS) {
            int  g    = e / K;
            int  j    = e - g * K;
            int  m    = s_gm[g];
            bool val  = j < min(s_cnt[g], K);
            int  o    = (b * M + m) * K + j;
            out[        o] = val ? (float)s_ti[g * TOPK + j] : -1.0f;
            out[    S + o] = val ? (float)m                  : -1.0f;
            out[2 * S + o] = val ? 1.0f : 0.0f;
            out[3 * S + o] = val ? s_tv[g * TOPK + j]        : 0.0f;
        }
    }
}

// ---------------------------------------------------------------------------
extern "C" void kernel_launch(void* const* d_in, const int* in_sizes, int n_in,
                              void* d_out, int out_size) {
    const float4* props   = (const float4*)d_in[2];
    const int*    pinds   = (const int*)   d_in[3];
    const int*    glabels = (const int*)   d_in[4];
    const float4* gts     = (const float4*)d_in[5];

    const int B  = BB;
    int BN = in_sizes[3];
    int BM = in_sizes[4];
    int N  = BN / B;
    int M  = BM / B;
    int K  = out_size / (4 * BM);
    if (K > TOPK) K = TOPK;
    if (K < 1)    K = 1;

    k_bucket<<<dim3(NL, B), THREADS>>>(props, gts, pinds, glabels,
                                       (float*)d_out, N, M, B, K);
}

// round 11
// speedup vs baseline: 1.7222x; 1.0639x over previous
#include <cuda_runtime.h>

// ---------------------------------------------------------------------------
// DECOLA Stage2 assigner — single kernel, one block per (label, batch) bucket.
//
// Key fact: match = (gt_label == prompt_ind), so the entire assignment
// decomposes per (batch,label) bucket: a GT only ever interacts with
// proposals of its own label, best_gt for a proposal is within its label's
// GTs, and each GT's output row is produced by exactly one bucket. Hence one
// self-contained block per bucket, chip-wide grid (128x16 = 2048 blocks),
// zero global scratch, zero inter-kernel traffic, ONE launch.
//
// Inputs (metadata order):
//   0: pred_logits_match (B,N,1) f32   -- unused
//   1: pred_boxes        (B,N,4) f32   -- unused
//   2: init_reference    (B,N,4) f32   -- proposals (cxcywh)
//   3: prompt_inds       (B,N)   i32
//   4: gt_labels         (B,M)   i32
//   5: gt_boxes          (B,M,4) f32
//   6: max_k             scalar  i32   (k derived from out_size)
// Output: concat(rows, cols, valid, sel_iou) each (B,M,k), float32.
// ---------------------------------------------------------------------------

#define BB      16            // batch (fixed for this problem)
#define NL      128           // label slots (L=80 < 128)
#define PCAP    192           // proposals per bucket cap (mean 37.5, sd 6 -> 25 sigma)
#define GCAP    32            // gts per bucket cap (mean 3.75, sd 1.9)
#define TOPK    4
#define THREADS 128
#define IMAXI   0x7fffffff

// IoU from explicit _rn intrinsics. Rows pass and cols pass call this same
// function on the SAME smem-resident box bits, so lq's (v == gmax) equality
// is exact by construction.
__device__ __forceinline__ float iou_fn(float4 g, float ga, float4 p, float pa) {
    float x0 = fmaxf(g.x, p.x);
    float y0 = fmaxf(g.y, p.y);
    float x1 = fminf(g.z, p.z);
    float y1 = fminf(g.w, p.w);
    float w  = fmaxf(__fsub_rn(x1, x0), 0.0f);
    float h  = fmaxf(__fsub_rn(y1, y0), 0.0f);
    float it = __fmul_rn(w, h);
    float un = __fsub_rn(__fadd_rn(ga, pa), it);
    return __fdiv_rn(it, fmaxf(un, 1e-9f));
}

// BRANCHLESS insert of (v,i) into a 4-entry list sorted by (value desc,
// index asc): compare-carry chain, pure setp/sel. Strict total order
// (indices distinct) -> insert-order independent; matches jax.lax.top_k
// stability (lower index first among equal values).
__device__ __forceinline__ void ins4(float v, int i, float tv[TOPK], int ti[TOPK]) {
#pragma unroll
    for (int j = 0; j < TOPK; j++) {
        bool sw = (v > tv[j]) || (v == tv[j] && i < ti[j]);
        float cv = sw ? tv[j] : v;
        int   ci = sw ? ti[j] : i;
        tv[j] = sw ? v : tv[j];
        ti[j] = sw ? i : ti[j];
        v = cv; i = ci;
    }
}

__device__ __forceinline__ float4 cxcywh_to_xyxy(float4 c) {
    float4 x;
    x.x = c.x - 0.5f * c.z; x.y = c.y - 0.5f * c.w;
    x.z = c.x + 0.5f * c.z; x.w = c.y + 0.5f * c.w;
    return x;
}

__global__ __launch_bounds__(THREADS)
void k_bucket(const float4* __restrict__ props,
              const float4* __restrict__ gts,
              const int*    __restrict__ pinds,
              const int*    __restrict__ glabels,
              float*        __restrict__ out,
              int N, int M, int B, int K) {
    __shared__ int    s_pcnt, s_gcnt;
    __shared__ int    s_pn  [PCAP];   // proposal indices n
    __shared__ float4 s_pbox[PCAP];
    __shared__ float  s_pa  [PCAP];
    __shared__ int    s_gm  [GCAP];   // gt indices m
    __shared__ float4 s_gbox[GCAP];
    __shared__ float  s_ga  [GCAP];
    __shared__ float  s_gmax[GCAP];
    __shared__ float  s_tv  [GCAP * TOPK];
    __shared__ int    s_ti  [GCAP * TOPK];
    __shared__ int    s_cnt [GCAP];

    const int l   = blockIdx.x;       // label
    const int b   = blockIdx.y;       // batch
    const int tid = threadIdx.x;

    if (tid == 0) { s_pcnt = 0; s_gcnt = 0; }
    __syncthreads();

    // ---- scan gt labels; early-exit if this label has no GT ----
    for (int m = tid; m < M; m += THREADS) {
        if (glabels[b * M + m] == l) {
            int s = atomicAdd(&s_gcnt, 1);
            if (s < GCAP) s_gm[s] = m;
        }
    }
    __syncthreads();
    int gcnt = min(s_gcnt, GCAP);
    if (gcnt == 0) return;            // no GT of this label: no outputs here

    // ---- scan prompt_inds for matching proposals (coalesced, L2-broadcast) ----
    for (int n = tid; n < N; n += THREADS) {
        if (pinds[b * N + n] == l) {
            int s = atomicAdd(&s_pcnt, 1);
            if (s < PCAP) s_pn[s] = n;
        }
    }
    __syncthreads();
    int pcnt = min(s_pcnt, PCAP);

    // ---- load + convert matched boxes into smem (each read exactly once chip-wide) ----
    for (int i = tid; i < pcnt; i += THREADS) {
        float4 x = cxcywh_to_xyxy(props[b * N + s_pn[i]]);
        s_pbox[i] = x;
        s_pa [i]  = __fmul_rn(__fsub_rn(x.z, x.x), __fsub_rn(x.w, x.y));
    }
    for (int i = tid; i < gcnt; i += THREADS) {
        float4 x = cxcywh_to_xyxy(gts[b * M + s_gm[i]]);
        s_gbox[i] = x;
        s_ga [i]  = __fmul_rn(__fsub_rn(x.z, x.x), __fsub_rn(x.w, x.y));
        s_cnt[i]  = 0;
    }
    __syncthreads();

    // ---- rows pass: one warp per GT, lanes stride proposals, butterfly top-4 ----
    {
        int w    = tid >> 5;
        int lane = tid & 31;
        for (int g = w; g < gcnt; g += THREADS / 32) {   // warp-uniform trip count
            float4 gb = s_gbox[g];
            float  ga = s_ga[g];
            float tv[TOPK] = {-1.f, -1.f, -1.f, -1.f};
            int   ti[TOPK] = {IMAXI, IMAXI, IMAXI, IMAXI};
            for (int e = lane; e < pcnt; e += 32) {
                float v = iou_fn(gb, ga, s_pbox[e], s_pa[e]);
                ins4(v, s_pn[e], tv, ti);
            }
#pragma unroll
            for (int off = 16; off > 0; off >>= 1) {
                float ov[TOPK]; int oi[TOPK];
#pragma unroll
                for (int j = 0; j < TOPK; j++) {
                    ov[j] = __shfl_xor_sync(0xffffffffu, tv[j], off);
                    oi[j] = __shfl_xor_sync(0xffffffffu, ti[j], off);
                }
#pragma unroll
                for (int j = 0; j < TOPK; j++) ins4(ov[j], oi[j], tv, ti);
            }
            if (lane == 0) {
                s_gmax[g] = tv[0];        // -1 when bucket has no proposals (== ref NEG)
#pragma unroll
                for (int j = 0; j < TOPK; j++) {
                    s_tv[g * TOPK + j] = tv[j];
                    s_ti[g * TOPK + j] = ti[j];
                }
            }
        }
    }
    __syncthreads();

    // ---- cols pass: per matched proposal, argmax over bucket GTs + lq + counts ----
    for (int i = tid; i < pcnt; i += THREADS) {
        float4 p  = s_pbox[i];
        float  pa = s_pa[i];
        float best = -2.0f;
        int   bgm  = IMAXI;   // gt index m for tie-break (JAX first-index argmax)
        int   bgs  = 0;       // gt slot for s_cnt
        bool  lq   = false;
        for (int e = 0; e < gcnt; e++) {
            float v = iou_fn(s_gbox[e], s_ga[e], p, pa);
            int   m = s_gm[e];
            // lexicographic (v desc, m asc): equals first-index argmax over
            // matched rows; unmatched rows (-1) never beat a matched iou>=0,
            // and pos=false when no match exists (handled by bucket scoping).
            bool bt = (v > best) || (v == best && m < bgm);
            best = bt ? v : best;
            bgm  = bt ? m : bgm;
            bgs  = bt ? e : bgs;
            lq   = lq || (v == s_gmax[e]);    // bitwise: same fn, same smem bits
        }
        if (best >= 0.6f || lq) atomicAdd(&s_cnt[bgs], 1);
    }
    __syncthreads();

    // ---- output: rows | cols | valid | sel_iou for this bucket's GTs ----
    {
        int S = B * M * K;
        for (int e = tid; e < gcnt * K; e += THREADS) {
            int  g    = e / K;
            int  j    = e - g * K;
            int  m    = s_gm[g];
            bool val  = j < min(s_cnt[g], K);
            int  o    = (b * M + m) * K + j;
            out[        o] = val ? (float)s_ti[g * TOPK + j] : -1.0f;
            out[    S + o] = val ? (float)m                  : -1.0f;
            out[2 * S + o] = val ? 1.0f : 0.0f;
            out[3 * S + o] = val ? s_tv[g * TOPK + j]        : 0.0f;
        }
    }
}

// ---------------------------------------------------------------------------
extern "C" void kernel_launch(void* const* d_in, const int* in_sizes, int n_in,
                              void* d_out, int out_size) {
    const float4* props   = (const float4*)d_in[2];
    const int*    pinds   = (const int*)   d_in[3];
    const int*    glabels = (const int*)   d_in[4];
    const float4* gts     = (const float4*)d_in[5];

    const int B  = BB;
    int BN = in_sizes[3];
    int BM = in_sizes[4];
    int N  = BN / B;
    int M  = BM / B;
    int K  = out_size / (4 * BM);
    if (K > TOPK) K = TOPK;
    if (K < 1)    K = 1;

    k_bucket<<<dim3(NL, B), THREADS>>>(props, gts, pinds, glabels,
                                       (float*)d_out, N, M, B, K);
}